// round 1
// baseline (speedup 1.0000x reference)
#include <cuda_runtime.h>
#include <cuda_fp16.h>
#include <cstdint>

#define BATCH     4
#define NHEAD     16
#define SEQ       2048
#define DHEAD     64
#define ROWSTRIDE 3072   // 3 * N_STATE
#define NSTATE    1024
#define BM        64
#define BN        64
#define NTHREADS  128
#define KPAD      72     // padded row length in halves -> conflict-free frag loads

__device__ __forceinline__ uint32_t h2pack(float lo, float hi) {
    __half2 h = __floats2half2_rn(lo, hi);
    return *reinterpret_cast<uint32_t*>(&h);
}

// split a float pair into fp16 hi + fp16 residual(lo) packed as b32 each
__device__ __forceinline__ void split2(float fx, float fy, uint32_t& hi, uint32_t& lo) {
    __half hx = __float2half_rn(fx);
    __half hy = __float2half_rn(fy);
    __half2 hh = __halves2half2(hx, hy);
    hi = *reinterpret_cast<uint32_t*>(&hh);
    lo = h2pack(fx - __half2float(hx), fy - __half2float(hy));
}

__device__ __forceinline__ void mma16816(float* c, const uint32_t* a, uint32_t b0, uint32_t b1) {
    asm volatile(
        "mma.sync.aligned.m16n8k16.row.col.f32.f16.f16.f32 "
        "{%0,%1,%2,%3}, {%4,%5,%6,%7}, {%8,%9}, {%0,%1,%2,%3};"
        : "+f"(c[0]), "+f"(c[1]), "+f"(c[2]), "+f"(c[3])
        : "r"(a[0]), "r"(a[1]), "r"(a[2]), "r"(a[3]), "r"(b0), "r"(b1));
}

__global__ __launch_bounds__(NTHREADS)
void fa_kernel(const float* __restrict__ x, float* __restrict__ out) {
    // K tile (hi/lo) in natural [key][dim]; V tile (hi/lo) transposed [dim][key]
    __shared__ __half Kh[BN][KPAD];
    __shared__ __half Kl[BN][KPAD];
    __shared__ __half Vh[DHEAD][KPAD];
    __shared__ __half Vl[DHEAD][KPAD];

    const int qtile = blockIdx.x;
    const int h     = blockIdx.y;
    const int b     = blockIdx.z;
    const int tid   = threadIdx.x;
    const int lane  = tid & 31;
    const int warp  = tid >> 5;
    const int g     = lane >> 2;   // groupID
    const int qr    = lane & 3;    // thread-in-group

    const size_t base = (size_t)b * SEQ * ROWSTRIDE + (size_t)h * DHEAD;
    const int row0 = qtile * BM + warp * 16 + g;   // second row is row0 + 8

    // ---- load Q fragments (hi/lo split), register resident across KV loop ----
    uint32_t qh[4][4], ql[4][4];
#pragma unroll
    for (int ks = 0; ks < 4; ks++) {
        const int c = ks * 16 + qr * 2;
        const float* p0 = x + base + (size_t)row0 * ROWSTRIDE + c;
        const float* p1 = x + base + (size_t)(row0 + 8) * ROWSTRIDE + c;
        float2 f0 = *reinterpret_cast<const float2*>(p0);
        float2 f1 = *reinterpret_cast<const float2*>(p1);
        float2 f2 = *reinterpret_cast<const float2*>(p0 + 8);
        float2 f3 = *reinterpret_cast<const float2*>(p1 + 8);
        split2(f0.x, f0.y, qh[ks][0], ql[ks][0]);
        split2(f1.x, f1.y, qh[ks][1], ql[ks][1]);
        split2(f2.x, f2.y, qh[ks][2], ql[ks][2]);
        split2(f3.x, f3.y, qh[ks][3], ql[ks][3]);
    }

    float o[8][4];
#pragma unroll
    for (int nd = 0; nd < 8; nd++)
#pragma unroll
        for (int e = 0; e < 4; e++) o[nd][e] = 0.f;

    float m0 = -INFINITY, m1 = -INFINITY;
    float l0 = 0.f, l1 = 0.f;

    const int rl0 = warp * 16 + g;   // local query row within tile
    const int rl1 = rl0 + 8;
    const int njt = qtile + 1;       // causal: only KV tiles <= q tile

    for (int j = 0; j < njt; j++) {
        const int kb = j * BN;
        // ---- cooperative load + fp16 split of K and V tiles ----
#pragma unroll
        for (int i = 0; i < 8; i++) {
            const int fi = i * NTHREADS + tid;
            const int r  = fi >> 4;
            const int c4 = (fi & 15) << 2;
            const float* rowp = x + base + (size_t)(kb + r) * ROWSTRIDE;
            float4 kv = *reinterpret_cast<const float4*>(rowp + NSTATE + c4);
            float4 vv = *reinterpret_cast<const float4*>(rowp + 2 * NSTATE + c4);
            const float kf[4] = {kv.x, kv.y, kv.z, kv.w};
            const float vf[4] = {vv.x, vv.y, vv.z, vv.w};
#pragma unroll
            for (int k = 0; k < 4; k++) {
                __half khh = __float2half_rn(kf[k]);
                Kh[r][c4 + k] = khh;
                Kl[r][c4 + k] = __float2half_rn(kf[k] - __half2float(khh));
                __half vhh = __float2half_rn(vf[k]);
                Vh[c4 + k][r] = vhh;                                  // transposed
                Vl[c4 + k][r] = __float2half_rn(vf[k] - __half2float(vhh));
            }
        }
        __syncthreads();

        // ---- S = scale * Q K^T  (3-term hi/lo split) ----
        float s[8][4];
#pragma unroll
        for (int nt = 0; nt < 8; nt++)
#pragma unroll
            for (int e = 0; e < 4; e++) s[nt][e] = 0.f;

#pragma unroll
        for (int ks = 0; ks < 4; ks++) {
#pragma unroll
            for (int nt = 0; nt < 8; nt++) {
                const __half* kp  = &Kh[nt * 8 + g][ks * 16 + qr * 2];
                const __half* kpl = &Kl[nt * 8 + g][ks * 16 + qr * 2];
                uint32_t b0h = *reinterpret_cast<const uint32_t*>(kp);
                uint32_t b1h = *reinterpret_cast<const uint32_t*>(kp + 8);
                uint32_t b0l = *reinterpret_cast<const uint32_t*>(kpl);
                uint32_t b1l = *reinterpret_cast<const uint32_t*>(kpl + 8);
                mma16816(s[nt], qh[ks], b0h, b1h);
                mma16816(s[nt], ql[ks], b0h, b1h);
                mma16816(s[nt], qh[ks], b0l, b1l);
            }
        }

        const bool diag = (j == qtile);
#pragma unroll
        for (int nt = 0; nt < 8; nt++) {
#pragma unroll
            for (int e = 0; e < 4; e++) s[nt][e] *= 0.125f;
            if (diag) {
                const int kl = nt * 8 + qr * 2;
                if (kl     > rl0) s[nt][0] = -1e30f;
                if (kl + 1 > rl0) s[nt][1] = -1e30f;
                if (kl     > rl1) s[nt][2] = -1e30f;
                if (kl + 1 > rl1) s[nt][3] = -1e30f;
            }
        }

        // ---- online softmax (rows g and g+8; quad shuffle reduce) ----
        float mx0 = -INFINITY, mx1 = -INFINITY;
#pragma unroll
        for (int nt = 0; nt < 8; nt++) {
            mx0 = fmaxf(mx0, fmaxf(s[nt][0], s[nt][1]));
            mx1 = fmaxf(mx1, fmaxf(s[nt][2], s[nt][3]));
        }
        mx0 = fmaxf(mx0, __shfl_xor_sync(0xffffffffu, mx0, 1));
        mx0 = fmaxf(mx0, __shfl_xor_sync(0xffffffffu, mx0, 2));
        mx1 = fmaxf(mx1, __shfl_xor_sync(0xffffffffu, mx1, 1));
        mx1 = fmaxf(mx1, __shfl_xor_sync(0xffffffffu, mx1, 2));

        const float mn0 = fmaxf(m0, mx0);
        const float mn1 = fmaxf(m1, mx1);
        const float a0 = __expf(m0 - mn0);
        const float a1 = __expf(m1 - mn1);
        m0 = mn0; m1 = mn1;

        float sum0 = 0.f, sum1 = 0.f;
#pragma unroll
        for (int nt = 0; nt < 8; nt++) {
            s[nt][0] = __expf(s[nt][0] - m0); sum0 += s[nt][0];
            s[nt][1] = __expf(s[nt][1] - m0); sum0 += s[nt][1];
            s[nt][2] = __expf(s[nt][2] - m1); sum1 += s[nt][2];
            s[nt][3] = __expf(s[nt][3] - m1); sum1 += s[nt][3];
        }
        sum0 += __shfl_xor_sync(0xffffffffu, sum0, 1);
        sum0 += __shfl_xor_sync(0xffffffffu, sum0, 2);
        sum1 += __shfl_xor_sync(0xffffffffu, sum1, 1);
        sum1 += __shfl_xor_sync(0xffffffffu, sum1, 2);
        l0 = l0 * a0 + sum0;
        l1 = l1 * a1 + sum1;

#pragma unroll
        for (int nd = 0; nd < 8; nd++) {
            o[nd][0] *= a0; o[nd][1] *= a0;
            o[nd][2] *= a1; o[nd][3] *= a1;
        }

        // ---- O += P V  (3-term hi/lo split) ----
#pragma unroll
        for (int ks2 = 0; ks2 < 4; ks2++) {
            const int n2 = ks2 * 2;
            uint32_t pah[4], pal[4];
            split2(s[n2][0],     s[n2][1],     pah[0], pal[0]);
            split2(s[n2][2],     s[n2][3],     pah[1], pal[1]);
            split2(s[n2 + 1][0], s[n2 + 1][1], pah[2], pal[2]);
            split2(s[n2 + 1][2], s[n2 + 1][3], pah[3], pal[3]);
#pragma unroll
            for (int nd = 0; nd < 8; nd++) {
                const __half* vp  = &Vh[nd * 8 + g][ks2 * 16 + qr * 2];
                const __half* vpl = &Vl[nd * 8 + g][ks2 * 16 + qr * 2];
                uint32_t b0h = *reinterpret_cast<const uint32_t*>(vp);
                uint32_t b1h = *reinterpret_cast<const uint32_t*>(vp + 8);
                uint32_t b0l = *reinterpret_cast<const uint32_t*>(vpl);
                uint32_t b1l = *reinterpret_cast<const uint32_t*>(vpl + 8);
                mma16816(o[nd], pah, b0h, b1h);
                mma16816(o[nd], pal, b0h, b1h);
                mma16816(o[nd], pah, b0l, b1l);
            }
        }
        __syncthreads();
    }

    // ---- epilogue: normalize and store fp32 ----
    const float inv0 = 1.f / l0;
    const float inv1 = 1.f / l1;
    float* ob = out + (size_t)b * SEQ * NSTATE + (size_t)h * DHEAD;
#pragma unroll
    for (int nd = 0; nd < 8; nd++) {
        const int dcol = nd * 8 + qr * 2;
        float2 v0; v0.x = o[nd][0] * inv0; v0.y = o[nd][1] * inv0;
        float2 v1; v1.x = o[nd][2] * inv1; v1.y = o[nd][3] * inv1;
        *reinterpret_cast<float2*>(ob + (size_t)row0 * NSTATE + dcol) = v0;
        *reinterpret_cast<float2*>(ob + (size_t)(row0 + 8) * NSTATE + dcol) = v1;
    }
}

extern "C" void kernel_launch(void* const* d_in, const int* in_sizes, int n_in,
                              void* d_out, int out_size) {
    const float* x = (const float*)d_in[0];
    // d_in[1] is the causal mask; known-static (tril), handled analytically.
    float* out = (float*)d_out;
    dim3 grid(SEQ / BM, NHEAD, BATCH);
    fa_kernel<<<grid, NTHREADS>>>(x, out);
}

// round 2
// speedup vs baseline: 1.7962x; 1.7962x over previous
#include <cuda_runtime.h>
#include <cuda_fp16.h>
#include <cstdint>

#define BATCH     4
#define NHEAD     16
#define SEQ       2048
#define DHEAD     64
#define ROWSTRIDE 3072   // 3 * N_STATE
#define NSTATE    1024
#define BM        64
#define BN        64
#define NTHREADS  128
#define KPAD      72     // padded row length in halves (144B): LDSM conflict-free

__device__ __forceinline__ uint32_t h2pack(float lo, float hi) {
    __half2 h = __floats2half2_rn(lo, hi);
    return *reinterpret_cast<uint32_t*>(&h);
}

__device__ __forceinline__ void split2(float fx, float fy, uint32_t& hi, uint32_t& lo) {
    __half hx = __float2half_rn(fx);
    __half hy = __float2half_rn(fy);
    __half2 hh = __halves2half2(hx, hy);
    hi = *reinterpret_cast<uint32_t*>(&hh);
    lo = h2pack(fx - __half2float(hx), fy - __half2float(hy));
}

__device__ __forceinline__ void mma16816(float* c, const uint32_t* a, uint32_t b0, uint32_t b1) {
    asm volatile(
        "mma.sync.aligned.m16n8k16.row.col.f32.f16.f16.f32 "
        "{%0,%1,%2,%3}, {%4,%5,%6,%7}, {%8,%9}, {%0,%1,%2,%3};"
        : "+f"(c[0]), "+f"(c[1]), "+f"(c[2]), "+f"(c[3])
        : "r"(a[0]), "r"(a[1]), "r"(a[2]), "r"(a[3]), "r"(b0), "r"(b1));
}

__device__ __forceinline__ void ldsm_x4(uint32_t& r0, uint32_t& r1, uint32_t& r2, uint32_t& r3,
                                        uint32_t addr) {
    asm volatile("ldmatrix.sync.aligned.m8n8.x4.shared.b16 {%0,%1,%2,%3}, [%4];"
                 : "=r"(r0), "=r"(r1), "=r"(r2), "=r"(r3) : "r"(addr));
}

__device__ __forceinline__ void ldsm_x4_t(uint32_t& r0, uint32_t& r1, uint32_t& r2, uint32_t& r3,
                                          uint32_t addr) {
    asm volatile("ldmatrix.sync.aligned.m8n8.x4.trans.shared.b16 {%0,%1,%2,%3}, [%4];"
                 : "=r"(r0), "=r"(r1), "=r"(r2), "=r"(r3) : "r"(addr));
}

__global__ __launch_bounds__(NTHREADS, 4)
void fa_kernel(const float* __restrict__ x, float* __restrict__ out) {
    // All tiles natural [key][dim]; V fragments come via ldmatrix.trans
    __shared__ alignas(16) __half Kh[BN][KPAD];
    __shared__ alignas(16) __half Kl[BN][KPAD];
    __shared__ alignas(16) __half Vh[BN][KPAD];
    __shared__ alignas(16) __half Vl[BN][KPAD];

    const int qtile = blockIdx.x;
    const int h     = blockIdx.y;
    const int b     = blockIdx.z;
    const int tid   = threadIdx.x;
    const int lane  = tid & 31;
    const int warp  = tid >> 5;
    const int g     = lane >> 2;   // groupID
    const int qr    = lane & 3;    // thread-in-group

    const size_t base = (size_t)b * SEQ * ROWSTRIDE + (size_t)h * DHEAD;
    const int row0 = qtile * BM + warp * 16 + g;

    // ldmatrix per-lane address selectors
    const int r8 = lane & 7;
    // K (non-trans): row = nt*8 + ((lane>>4)&1)*8 + r8 ; col = ks*16 + ((lane>>3)&1)*8
    const int krow = (((lane >> 4) & 1) << 3) + r8;
    const int kcol = ((lane >> 3) & 1) << 3;
    // V (trans): row = ks2*16 + ((lane>>3)&1)*8 + r8 ; col = nd*8 + ((lane>>4)&1)*8
    const int vrow = (((lane >> 3) & 1) << 3) + r8;
    const int vcol = ((lane >> 4) & 1) << 3;

    const uint32_t aKh = (uint32_t)__cvta_generic_to_shared(&Kh[krow][kcol]);
    const uint32_t aKl = (uint32_t)__cvta_generic_to_shared(&Kl[krow][kcol]);
    const uint32_t aVh = (uint32_t)__cvta_generic_to_shared(&Vh[vrow][vcol]);
    const uint32_t aVl = (uint32_t)__cvta_generic_to_shared(&Vl[vrow][vcol]);

    // ---- load Q fragments (hi/lo split), register resident ----
    uint32_t qh[4][4], ql[4][4];
#pragma unroll
    for (int ks = 0; ks < 4; ks++) {
        const int c = ks * 16 + qr * 2;
        const float* p0 = x + base + (size_t)row0 * ROWSTRIDE + c;
        const float* p1 = x + base + (size_t)(row0 + 8) * ROWSTRIDE + c;
        float2 f0 = *reinterpret_cast<const float2*>(p0);
        float2 f1 = *reinterpret_cast<const float2*>(p1);
        float2 f2 = *reinterpret_cast<const float2*>(p0 + 8);
        float2 f3 = *reinterpret_cast<const float2*>(p1 + 8);
        split2(f0.x, f0.y, qh[ks][0], ql[ks][0]);
        split2(f1.x, f1.y, qh[ks][1], ql[ks][1]);
        split2(f2.x, f2.y, qh[ks][2], ql[ks][2]);
        split2(f3.x, f3.y, qh[ks][3], ql[ks][3]);
    }

    float o[8][4];
#pragma unroll
    for (int nd = 0; nd < 8; nd++)
#pragma unroll
        for (int e = 0; e < 4; e++) o[nd][e] = 0.f;

    float m0 = -INFINITY, m1 = -INFINITY;
    float l0 = 0.f, l1 = 0.f;

    const int rl0 = warp * 16 + g;
    const int rl1 = rl0 + 8;
    const int njt = qtile + 1;

    for (int j = 0; j < njt; j++) {
        const int kb = j * BN;
        // ---- cooperative load + fp16 hi/lo split, vectorized STS.64 ----
#pragma unroll
        for (int i = 0; i < 8; i++) {
            const int fi = i * NTHREADS + tid;
            const int r  = fi >> 4;
            const int c4 = (fi & 15) << 2;
            const float* rowp = x + base + (size_t)(kb + r) * ROWSTRIDE;
            float4 kv = *reinterpret_cast<const float4*>(rowp + NSTATE + c4);
            float4 vv = *reinterpret_cast<const float4*>(rowp + 2 * NSTATE + c4);

            __half2 kh01 = __floats2half2_rn(kv.x, kv.y);
            __half2 kh23 = __floats2half2_rn(kv.z, kv.w);
            float2 kb01 = __half22float2(kh01);
            float2 kb23 = __half22float2(kh23);
            __half2 kl01 = __floats2half2_rn(kv.x - kb01.x, kv.y - kb01.y);
            __half2 kl23 = __floats2half2_rn(kv.z - kb23.x, kv.w - kb23.y);

            __half2 vh01 = __floats2half2_rn(vv.x, vv.y);
            __half2 vh23 = __floats2half2_rn(vv.z, vv.w);
            float2 vb01 = __half22float2(vh01);
            float2 vb23 = __half22float2(vh23);
            __half2 vl01 = __floats2half2_rn(vv.x - vb01.x, vv.y - vb01.y);
            __half2 vl23 = __floats2half2_rn(vv.z - vb23.x, vv.w - vb23.y);

            uint2 pk_h = {*reinterpret_cast<uint32_t*>(&kh01), *reinterpret_cast<uint32_t*>(&kh23)};
            uint2 pk_l = {*reinterpret_cast<uint32_t*>(&kl01), *reinterpret_cast<uint32_t*>(&kl23)};
            uint2 pv_h = {*reinterpret_cast<uint32_t*>(&vh01), *reinterpret_cast<uint32_t*>(&vh23)};
            uint2 pv_l = {*reinterpret_cast<uint32_t*>(&vl01), *reinterpret_cast<uint32_t*>(&vl23)};
            *reinterpret_cast<uint2*>(&Kh[r][c4]) = pk_h;
            *reinterpret_cast<uint2*>(&Kl[r][c4]) = pk_l;
            *reinterpret_cast<uint2*>(&Vh[r][c4]) = pv_h;
            *reinterpret_cast<uint2*>(&Vl[r][c4]) = pv_l;
        }
        __syncthreads();

        // ---- S = scale * Q K^T (3-term hi/lo split), LDSM.x4 fragments ----
        float s[8][4];
#pragma unroll
        for (int nt = 0; nt < 8; nt++)
#pragma unroll
            for (int e = 0; e < 4; e++) s[nt][e] = 0.f;

#pragma unroll
        for (int ks = 0; ks < 4; ks++) {
#pragma unroll
            for (int ntp = 0; ntp < 4; ntp++) {
                const int nt = ntp * 2;
                const uint32_t off = (uint32_t)((nt * 8 * KPAD + ks * 16) * 2);
                uint32_t bh0, bh1, bh2, bh3, bl0, bl1, bl2, bl3;
                ldsm_x4(bh0, bh1, bh2, bh3, aKh + off);
                ldsm_x4(bl0, bl1, bl2, bl3, aKl + off);
                mma16816(s[nt],     qh[ks], bh0, bh1);
                mma16816(s[nt],     ql[ks], bh0, bh1);
                mma16816(s[nt],     qh[ks], bl0, bl1);
                mma16816(s[nt + 1], qh[ks], bh2, bh3);
                mma16816(s[nt + 1], ql[ks], bh2, bh3);
                mma16816(s[nt + 1], qh[ks], bl2, bl3);
            }
        }

        const bool diag = (j == qtile);
#pragma unroll
        for (int nt = 0; nt < 8; nt++) {
#pragma unroll
            for (int e = 0; e < 4; e++) s[nt][e] *= 0.125f;
            if (diag) {
                const int kl = nt * 8 + qr * 2;
                if (kl     > rl0) s[nt][0] = -1e30f;
                if (kl + 1 > rl0) s[nt][1] = -1e30f;
                if (kl     > rl1) s[nt][2] = -1e30f;
                if (kl + 1 > rl1) s[nt][3] = -1e30f;
            }
        }

        // ---- online softmax ----
        float mx0 = -INFINITY, mx1 = -INFINITY;
#pragma unroll
        for (int nt = 0; nt < 8; nt++) {
            mx0 = fmaxf(mx0, fmaxf(s[nt][0], s[nt][1]));
            mx1 = fmaxf(mx1, fmaxf(s[nt][2], s[nt][3]));
        }
        mx0 = fmaxf(mx0, __shfl_xor_sync(0xffffffffu, mx0, 1));
        mx0 = fmaxf(mx0, __shfl_xor_sync(0xffffffffu, mx0, 2));
        mx1 = fmaxf(mx1, __shfl_xor_sync(0xffffffffu, mx1, 1));
        mx1 = fmaxf(mx1, __shfl_xor_sync(0xffffffffu, mx1, 2));

        const float mn0 = fmaxf(m0, mx0);
        const float mn1 = fmaxf(m1, mx1);
        const float a0 = __expf(m0 - mn0);
        const float a1 = __expf(m1 - mn1);
        m0 = mn0; m1 = mn1;

        float sum0 = 0.f, sum1 = 0.f;
#pragma unroll
        for (int nt = 0; nt < 8; nt++) {
            s[nt][0] = __expf(s[nt][0] - m0); sum0 += s[nt][0];
            s[nt][1] = __expf(s[nt][1] - m0); sum0 += s[nt][1];
            s[nt][2] = __expf(s[nt][2] - m1); sum1 += s[nt][2];
            s[nt][3] = __expf(s[nt][3] - m1); sum1 += s[nt][3];
        }
        sum0 += __shfl_xor_sync(0xffffffffu, sum0, 1);
        sum0 += __shfl_xor_sync(0xffffffffu, sum0, 2);
        sum1 += __shfl_xor_sync(0xffffffffu, sum1, 1);
        sum1 += __shfl_xor_sync(0xffffffffu, sum1, 2);
        l0 = l0 * a0 + sum0;
        l1 = l1 * a1 + sum1;

#pragma unroll
        for (int nd = 0; nd < 8; nd++) {
            o[nd][0] *= a0; o[nd][1] *= a0;
            o[nd][2] *= a1; o[nd][3] *= a1;
        }

        // ---- O += P V (3-term split), V via LDSM.x4.trans ----
#pragma unroll
        for (int ks2 = 0; ks2 < 4; ks2++) {
            const int n2 = ks2 * 2;
            uint32_t pah[4], pal[4];
            split2(s[n2][0],     s[n2][1],     pah[0], pal[0]);
            split2(s[n2][2],     s[n2][3],     pah[1], pal[1]);
            split2(s[n2 + 1][0], s[n2 + 1][1], pah[2], pal[2]);
            split2(s[n2 + 1][2], s[n2 + 1][3], pah[3], pal[3]);
#pragma unroll
            for (int ndp = 0; ndp < 4; ndp++) {
                const int nd = ndp * 2;
                const uint32_t off = (uint32_t)((ks2 * 16 * KPAD + nd * 8) * 2);
                uint32_t bh0, bh1, bh2, bh3, bl0, bl1, bl2, bl3;
                ldsm_x4_t(bh0, bh1, bh2, bh3, aVh + off);
                ldsm_x4_t(bl0, bl1, bl2, bl3, aVl + off);
                mma16816(o[nd],     pah, bh0, bh1);
                mma16816(o[nd],     pal, bh0, bh1);
                mma16816(o[nd],     pah, bl0, bl1);
                mma16816(o[nd + 1], pah, bh2, bh3);
                mma16816(o[nd + 1], pal, bh2, bh3);
                mma16816(o[nd + 1], pah, bl2, bl3);
            }
        }
        __syncthreads();
    }

    // ---- epilogue ----
    const float inv0 = 1.f / l0;
    const float inv1 = 1.f / l1;
    float* ob = out + (size_t)b * SEQ * NSTATE + (size_t)h * DHEAD;
#pragma unroll
    for (int nd = 0; nd < 8; nd++) {
        const int dcol = nd * 8 + qr * 2;
        float2 v0; v0.x = o[nd][0] * inv0; v0.y = o[nd][1] * inv0;
        float2 v1; v1.x = o[nd][2] * inv1; v1.y = o[nd][3] * inv1;
        *reinterpret_cast<float2*>(ob + (size_t)row0 * NSTATE + dcol) = v0;
        *reinterpret_cast<float2*>(ob + (size_t)(row0 + 8) * NSTATE + dcol) = v1;
    }
}

extern "C" void kernel_launch(void* const* d_in, const int* in_sizes, int n_in,
                              void* d_out, int out_size) {
    const float* x = (const float*)d_in[0];
    float* out = (float*)d_out;
    dim3 grid(SEQ / BM, NHEAD, BATCH);
    fa_kernel<<<grid, NTHREADS>>>(x, out);
}